// round 15
// baseline (speedup 1.0000x reference)
#include <cuda_runtime.h>
#include <cuda_fp16.h>

// Erosion2D: out[b,y,x,c] = min_{dy,dx in [0,4)} x[y+dy-1, x+dx-1, c] - w[3-dy, 3-dx, c]
// Warp-specialized pipelined version:
//   - 8 consumer warps (256 thr): fp16x2 compute identical to the 100.8us kernel
//   - 4 producer warps (128 thr): stage NEXT x-adjacent tile (LDG.128 -> F2FP -> STS)
//     into a double-buffered smem tile while consumers compute the current one.
//   - named-barrier full/empty handshake (ids 1+b / 3+b, count 384)
// Each block walks NT=4 x-adjacent 16x16 tiles -> DRAM loads flow continuously.

#define BIGF 1e30f

constexpr int B = 8, H = 512, W = 512, C = 32;
constexpr int TY = 16, TX = 16, NT = 4;    // 4 x-tiles per block (x-span 64)
constexpr int SR = TY + 3;                 // 19 smem rows
constexpr int SP = TX + 3;                 // 19 smem pixel-columns
constexpr int PIX_H2 = C / 2;              // 16 half2 per pixel
constexpr int SMEM_H2 = SR * SP * PIX_H2;  // 5776 half2 = 23104 B per buffer
constexpr int THREADS = 384;               // 8 consumer + 4 producer warps
constexpr int NCONS = 256;
constexpr int LOADS = SR * SP * (C / 4);   // 2888 float4 loads per tile

__device__ __forceinline__ unsigned h2u(__half2 h) {
    return reinterpret_cast<unsigned&>(h);
}
__device__ __forceinline__ void bar_sync(int id) {
    asm volatile("bar.sync %0, %1;" :: "r"(id), "n"(THREADS) : "memory");
}
__device__ __forceinline__ void bar_arrive(int id) {
    asm volatile("bar.arrive %0, %1;" :: "r"(id), "n"(THREADS) : "memory");
}

__global__ __launch_bounds__(THREADS, 4)
void erosion2d_kernel(const float* __restrict__ xin,
                      const float* __restrict__ wt,
                      float* __restrict__ out) {
    __shared__ __half2 tile[2 * SMEM_H2];   // double buffer, 46208 B

    const int bx = blockIdx.x;          // tile-group: 0..7 (x-span 64 each)
    const int by = blockIdx.y;          // y strip: 0..31
    const int b  = blockIdx.z;          // batch
    const int y0 = by * TY;
    const int tid = threadIdx.x;

    const float* xb = xin + (size_t)b * H * W * C;

    if (tid >= NCONS) {
        // ---------------- producer warps: stage tiles into alternating buffers ----
        const int tp = tid - NCONS;     // 0..127
        for (int t = 0; t < NT; t++) {
            const int bb = t & 1;
            if (t >= 2) bar_sync(3 + bb);          // wait: consumers done with buf bb
            const int tgx = bx * NT + t;           // global x-tile index 0..31
            const int x0 = tgx * TX;
            __half2* dst = tile + bb * SMEM_H2;
            const bool interior = (tgx > 0) & (tgx < (W / TX - 1)) &
                                  (by > 0) & (by < (H / TY - 1));
            if (interior) {
                #pragma unroll 4
                for (int i = tp; i < LOADS; i += 128) {
                    int r   = i / (SP * (C / 4));
                    int rem = i - r * (SP * (C / 4));
                    int p   = rem >> 3;            // pixel in row
                    int q   = rem & 7;             // channel quad
                    int gy = y0 - 1 + r;
                    int gx = x0 - 1 + p;
                    float4 v = *(const float4*)(xb + ((size_t)gy * W + gx) * C + q * 4);
                    __half2 h01 = __floats2half2_rn(v.x, v.y);
                    __half2 h23 = __floats2half2_rn(v.z, v.w);
                    int hi = (r * SP + p) * PIX_H2 + q * 2;
                    *(uint2*)(dst + hi) = make_uint2(h2u(h01), h2u(h23));
                }
            } else {
                #pragma unroll 4
                for (int i = tp; i < LOADS; i += 128) {
                    int r   = i / (SP * (C / 4));
                    int rem = i - r * (SP * (C / 4));
                    int p   = rem >> 3;
                    int q   = rem & 7;
                    int gy = y0 - 1 + r;
                    int gx = x0 - 1 + p;
                    float4 v;
                    if (gy >= 0 && gy < H && gx >= 0 && gx < W) {
                        v = *(const float4*)(xb + ((size_t)gy * W + gx) * C + q * 4);
                    } else {
                        v = make_float4(BIGF, BIGF, BIGF, BIGF);   // -> +inf in fp16
                    }
                    __half2 h01 = __floats2half2_rn(v.x, v.y);
                    __half2 h23 = __floats2half2_rn(v.z, v.w);
                    int hi = (r * SP + p) * PIX_H2 + q * 2;
                    *(uint2*)(dst + hi) = make_uint2(h2u(h01), h2u(h23));
                }
            }
            bar_arrive(1 + bb);                    // signal: buf bb full
        }
    } else {
        // ---------------- consumer warps: compute from staged buffers -------------
        const int cp = tid & 15;        // channel pair: channels 2*cp, 2*cp+1
        const int ty = tid >> 4;        // output row in tile: 0..15
        const int c0 = cp * 2;

        // negated reflected weights: nw[d][k] = -w[3-k][3-d][c0..c0+1] as half2
        __half2 nw[4][4];
        #pragma unroll
        for (int d = 0; d < 4; d++) {
            #pragma unroll
            for (int k = 0; k < 4; k++) {
                const float* wp = wt + ((3 - k) * 4 + (3 - d)) * C + c0;
                nw[d][k] = __floats2half2_rn(-wp[0], -wp[1]);
            }
        }

        const __half2 BIGH = __floats2half2_rn(BIGF, BIGF);   // +inf pair
        const int rowbase = ty * SP;

        for (int t = 0; t < NT; t++) {
            const int bb = t & 1;
            const int x0 = (bx * NT + t) * TX;
            bar_sync(1 + bb);                      // wait: buf bb staged

            const __half2* tl = tile + bb * SMEM_H2;
            float* op = out + (((size_t)(b * H + y0 + ty) * W + x0) * C) + c0;

            __half2 q0a = BIGH, q0b = BIGH, q0c = BIGH,
                    q1a = BIGH, q1b = BIGH, q2a = BIGH;

            #pragma unroll
            for (int s = 0; s < SP; s++) {
                __half2 r0 = tl[((rowbase) + s) * PIX_H2 + cp];
                __half2 r1 = tl[((rowbase + SP) + s) * PIX_H2 + cp];
                __half2 r2 = tl[((rowbase + 2 * SP) + s) * PIX_H2 + cp];
                __half2 r3 = tl[((rowbase + 3 * SP) + s) * PIX_H2 + cp];

                __half2 cd[4];
                #pragma unroll
                for (int d = 0; d < 4; d++) {
                    __half2 a0 = __hadd2(r0, nw[d][0]);
                    __half2 a1 = __hadd2(r1, nw[d][1]);
                    __half2 a2 = __hadd2(r2, nw[d][2]);
                    __half2 a3 = __hadd2(r3, nw[d][3]);
                    cd[d] = __hmin2(__hmin2(a0, a1), __hmin2(a2, a3));
                }

                if (s >= 3) {
                    __half2 o = __hmin2(__hmin2(q0a, q1a), __hmin2(q2a, cd[3]));
                    float2 of = __half22float2(o);
                    *(float2*)(op + (size_t)(s - 3) * C) = of;
                }

                q0a = q0b; q0b = q0c; q0c = cd[0];
                q1a = q1b; q1b = cd[1];
                q2a = cd[2];
            }

            bar_arrive(3 + bb);                    // signal: buf bb free
        }
    }
}

extern "C" void kernel_launch(void* const* d_in, const int* in_sizes, int n_in,
                              void* d_out, int out_size) {
    const float* x = (const float*)d_in[0];
    const float* w = (const float*)d_in[1];
    float* out = (float*)d_out;

    dim3 grid(W / (TX * NT), H / TY, B);   // 8 x 32 x 8 = 2048 blocks
    erosion2d_kernel<<<grid, THREADS>>>(x, w, out);
}

// round 17
// speedup vs baseline: 2.4677x; 2.4677x over previous
#include <cuda_runtime.h>
#include <cuda_fp16.h>

// Erosion2D: out[b,y,x,c] = min_{dy,dx in [0,4)} x[y+dy-1, x+dx-1, c] - w[3-dy, 3-dx, c]
// fp16x2 compute: smem tile staged as half2 (2 channels/reg), subtraction via __hadd2
// with pre-negated weights, packed __hmin2 mins, 3-deep register ring over columns.
// fp32 in/out. R14 base (96.9us) + streaming stores (st.global.cs protects L2 halo
// residency) + staging unroll 8 (MLP up). Resubmit of R16 (infra failure).

#define BIGF 1e30f

constexpr int B = 8, H = 512, W = 512, C = 32;
constexpr int TY = 16, TX = 16;
constexpr int SR = TY + 3;                 // 19 smem rows
constexpr int SP = TX + 3;                 // 19 smem pixel-columns
constexpr int PIX_H2 = C / 2;              // 16 half2 per pixel
constexpr int SMEM_H2 = SR * SP * PIX_H2;  // 5776 half2 = 23104 B
constexpr int THREADS = 256;

__device__ __forceinline__ unsigned h2u(__half2 h) {
    return reinterpret_cast<unsigned&>(h);
}
__device__ __forceinline__ void stcs64(float* p, float2 v) {
    asm volatile("st.global.cs.v2.f32 [%0], {%1, %2};" :: "l"(p), "f"(v.x), "f"(v.y) : "memory");
}

__global__ __launch_bounds__(THREADS, 6)
void erosion2d_kernel(const float* __restrict__ xin,
                      const float* __restrict__ wt,
                      float* __restrict__ out) {
    __shared__ __half2 tile[SMEM_H2];

    const int bx = blockIdx.x;          // x tile: 0..31
    const int by = blockIdx.y;          // y tile: 0..31
    const int b  = blockIdx.z;          // batch
    const int x0 = bx * TX;
    const int y0 = by * TY;
    const int tid = threadIdx.x;

    const float* xb = xin + (size_t)b * H * W * C;

    // ---------------- load halo tile into smem (fp32 -> fp16x2) ----------------
    const bool interior = (bx > 0) & (bx < (W / TX - 1)) & (by > 0) & (by < (H / TY - 1));
    constexpr int LOADS = SR * SP * (C / 4);   // float4 loads: 2888

    if (interior) {
        #pragma unroll 8
        for (int i = tid; i < LOADS; i += THREADS) {
            int r   = i / (SP * (C / 4));
            int rem = i - r * (SP * (C / 4));
            int p   = rem >> 3;            // pixel in row (C/4 == 8)
            int q   = rem & 7;             // channel quad
            int gy = y0 - 1 + r;
            int gx = x0 - 1 + p;
            float4 v = *(const float4*)(xb + ((size_t)gy * W + gx) * C + q * 4);
            __half2 h01 = __floats2half2_rn(v.x, v.y);
            __half2 h23 = __floats2half2_rn(v.z, v.w);
            int hi = (r * SP + p) * PIX_H2 + q * 2;
            *(uint2*)(tile + hi) = make_uint2(h2u(h01), h2u(h23));
        }
    } else {
        #pragma unroll 8
        for (int i = tid; i < LOADS; i += THREADS) {
            int r   = i / (SP * (C / 4));
            int rem = i - r * (SP * (C / 4));
            int p   = rem >> 3;
            int q   = rem & 7;
            int gy = y0 - 1 + r;
            int gx = x0 - 1 + p;
            float4 v;
            if (gy >= 0 && gy < H && gx >= 0 && gx < W) {
                v = *(const float4*)(xb + ((size_t)gy * W + gx) * C + q * 4);
            } else {
                v = make_float4(BIGF, BIGF, BIGF, BIGF);   // -> +inf in fp16
            }
            __half2 h01 = __floats2half2_rn(v.x, v.y);
            __half2 h23 = __floats2half2_rn(v.z, v.w);
            int hi = (r * SP + p) * PIX_H2 + q * 2;
            *(uint2*)(tile + hi) = make_uint2(h2u(h01), h2u(h23));
        }
    }

    // ---------------- weights (overlap with staging) ----------------
    const int cp = tid & 15;        // channel pair: channels 2*cp, 2*cp+1
    const int ty = tid >> 4;        // output row in tile: 0..15
    const int c0 = cp * 2;

    // negated reflected weights: nw[d][k] = -w[3-k][3-d][c0..c0+1] as half2
    __half2 nw[4][4];
    #pragma unroll
    for (int d = 0; d < 4; d++) {
        #pragma unroll
        for (int k = 0; k < 4; k++) {
            const float* wp = wt + ((3 - k) * 4 + (3 - d)) * C + c0;
            nw[d][k] = __floats2half2_rn(-wp[0], -wp[1]);
        }
    }

    __syncthreads();

    // ---------------- compute ----------------
    float* op = out + (((size_t)(b * H + y0 + ty) * W + x0) * C) + c0;

    // ring: q0a=c0(s-3) q0b=c0(s-2) q0c=c0(s-1); q1a=c1(s-2) q1b=c1(s-1); q2a=c2(s-1)
    const __half2 BIGH = __floats2half2_rn(BIGF, BIGF);   // +inf pair
    __half2 q0a = BIGH, q0b = BIGH, q0c = BIGH, q1a = BIGH, q1b = BIGH, q2a = BIGH;

    const int rowbase = ty * SP;

    #pragma unroll
    for (int s = 0; s < SP; s++) {
        // 4 input rows of smem column s (this thread's channel pair)
        __half2 r0 = tile[((rowbase) + s) * PIX_H2 + cp];
        __half2 r1 = tile[((rowbase + SP) + s) * PIX_H2 + cp];
        __half2 r2 = tile[((rowbase + 2 * SP) + s) * PIX_H2 + cp];
        __half2 r3 = tile[((rowbase + 3 * SP) + s) * PIX_H2 + cp];

        // column pass: cd[d] = min_k (r_k + nw[d][k])   (packed over 2 channels)
        __half2 cd[4];
        #pragma unroll
        for (int d = 0; d < 4; d++) {
            __half2 a0 = __hadd2(r0, nw[d][0]);
            __half2 a1 = __hadd2(r1, nw[d][1]);
            __half2 a2 = __hadd2(r2, nw[d][2]);
            __half2 a3 = __hadd2(r3, nw[d][3]);
            cd[d] = __hmin2(__hmin2(a0, a1), __hmin2(a2, a3));
        }

        // horizontal combine: out(j=s-3) = min(c0(j), c1(j+1), c2(j+2), c3(j+3))
        if (s >= 3) {
            __half2 o = __hmin2(__hmin2(q0a, q1a), __hmin2(q2a, cd[3]));
            float2 of = __half22float2(o);
            stcs64(op + (size_t)(s - 3) * C, of);   // evict-first: protect halo in L2
        }

        // shift rings (pure renaming under full unroll)
        q0a = q0b; q0b = q0c; q0c = cd[0];
        q1a = q1b; q1b = cd[1];
        q2a = cd[2];
    }
}

extern "C" void kernel_launch(void* const* d_in, const int* in_sizes, int n_in,
                              void* d_out, int out_size) {
    const float* x = (const float*)d_in[0];
    const float* w = (const float*)d_in[1];
    float* out = (float*)d_out;

    dim3 grid(W / TX, H / TY, B);   // 32 x 32 x 8 = 8192 blocks
    erosion2d_kernel<<<grid, THREADS>>>(x, w, out);
}